// round 1
// baseline (speedup 1.0000x reference)
#include <cuda_runtime.h>
#include <cuda_fp16.h>
#include <math_constants.h>

#define SEQ 4096
#define DH 64
#define NH 4
#define BM 128
#define BN 64
#define NTILES (SEQ / BN)   // 64
#define KPAD 72             // padded half stride (144B) -> conflict-free ldmatrix

// scratch: fp16 Q/K/V in (b,h,s,d) layout, affine applied (Q pre-scaled by scale*log2e)
__device__ __half g_Q[4 * NH * SEQ * DH];
__device__ __half g_K[4 * NH * SEQ * DH];
__device__ __half g_V[4 * NH * SEQ * DH];

__device__ __forceinline__ float fast_exp2(float x) {
    float y;
    asm("ex2.approx.f32 %0, %1;" : "=f"(y) : "f"(x));
    return y;
}

__device__ __forceinline__ unsigned pack_h2(float a, float b) {
    __half2 h = __floats2half2_rn(a, b);
    return *reinterpret_cast<unsigned*>(&h);
}

// ---------------- preprocess: affine + fp16 + (b,h,s,d) reshape ----------------
__global__ void preprocess_kernel(
    const float* __restrict__ q_in, const float* __restrict__ k_in, const float* __restrict__ v_in,
    const float* __restrict__ wq, const float* __restrict__ bq,
    const float* __restrict__ wk, const float* __restrict__ bk,
    const float* __restrict__ wv, const float* __restrict__ bv,
    int total4)
{
    const float qs = 0.125f * 1.44269504088896340736f;  // d^-0.5 * log2(e)
    int i4 = blockIdx.x * blockDim.x + threadIdx.x;
    if (i4 >= total4) return;
    int c4 = i4 & 63;          // 64 float4-groups per (b,s) row of 256 channels
    int s  = (i4 >> 6) & (SEQ - 1);
    int b  = i4 >> 18;
    int c  = c4 * 4;
    int h  = c >> 6;
    int d  = c & 63;
    int in_idx  = (b * SEQ + s) * 256 + c;
    int out_idx = ((b * NH + h) * SEQ + s) * DH + d;

    float4 qv = *(const float4*)(q_in + in_idx);
    float4 kv = *(const float4*)(k_in + in_idx);
    float4 vv = *(const float4*)(v_in + in_idx);

    float4 w, bb;
    uint2 p;

    w = *(const float4*)(wq + c); bb = *(const float4*)(bq + c);
    p.x = pack_h2((qv.x * w.x + bb.x) * qs, (qv.y * w.y + bb.y) * qs);
    p.y = pack_h2((qv.z * w.z + bb.z) * qs, (qv.w * w.w + bb.w) * qs);
    *(uint2*)(g_Q + out_idx) = p;

    w = *(const float4*)(wk + c); bb = *(const float4*)(bk + c);
    p.x = pack_h2(kv.x * w.x + bb.x, kv.y * w.y + bb.y);
    p.y = pack_h2(kv.z * w.z + bb.z, kv.w * w.w + bb.w);
    *(uint2*)(g_K + out_idx) = p;

    w = *(const float4*)(wv + c); bb = *(const float4*)(bv + c);
    p.x = pack_h2(vv.x * w.x + bb.x, vv.y * w.y + bb.y);
    p.y = pack_h2(vv.z * w.z + bb.z, vv.w * w.w + bb.w);
    *(uint2*)(g_V + out_idx) = p;
}

// ---------------- flash attention ----------------
__device__ __forceinline__ void mma16816(float c[4], const unsigned a[4], unsigned b0, unsigned b1) {
    asm volatile(
        "mma.sync.aligned.m16n8k16.row.col.f32.f16.f16.f32 "
        "{%0,%1,%2,%3},{%4,%5,%6,%7},{%8,%9},{%0,%1,%2,%3};\n"
        : "+f"(c[0]), "+f"(c[1]), "+f"(c[2]), "+f"(c[3])
        : "r"(a[0]), "r"(a[1]), "r"(a[2]), "r"(a[3]), "r"(b0), "r"(b1));
}

__device__ __forceinline__ void ldsm_x4(unsigned& r0, unsigned& r1, unsigned& r2, unsigned& r3, const __half* p) {
    unsigned addr = (unsigned)__cvta_generic_to_shared(p);
    asm volatile("ldmatrix.sync.aligned.m8n8.x4.shared.b16 {%0,%1,%2,%3}, [%4];\n"
                 : "=r"(r0), "=r"(r1), "=r"(r2), "=r"(r3) : "r"(addr));
}

__device__ __forceinline__ void ldsm_x4_t(unsigned& r0, unsigned& r1, unsigned& r2, unsigned& r3, const __half* p) {
    unsigned addr = (unsigned)__cvta_generic_to_shared(p);
    asm volatile("ldmatrix.sync.aligned.m8n8.x4.trans.shared.b16 {%0,%1,%2,%3}, [%4];\n"
                 : "=r"(r0), "=r"(r1), "=r"(r2), "=r"(r3) : "r"(addr));
}

__device__ __forceinline__ void cp16(__half* dst, const __half* src) {
    unsigned d = (unsigned)__cvta_generic_to_shared(dst);
    asm volatile("cp.async.cg.shared.global [%0], [%1], 16;\n" :: "r"(d), "l"(src));
}

__global__ void __launch_bounds__(256, 2) attn_kernel(
    float* __restrict__ out, const float* __restrict__ wp, const float* __restrict__ bp)
{
    __shared__ __half Ks[2][BN * KPAD];
    __shared__ __half Vs[2][BN * KPAD];

    const int tid  = threadIdx.x;
    const int w    = tid >> 5;
    const int lane = tid & 31;
    const int gid  = lane >> 2;   // 0..7
    const int tig  = lane & 3;    // 0..3

    const int bh = blockIdx.y;           // b*NH + h
    const int b  = bh >> 2;
    const int h  = bh & 3;
    const int q0 = blockIdx.x * BM;

    const __half* Qg = g_Q + bh * (SEQ * DH);
    const __half* Kg = g_K + bh * (SEQ * DH);
    const __half* Vg = g_V + bh * (SEQ * DH);

    // --- issue first two KV tiles (cp.async) ---
    {
        #pragma unroll
        for (int st = 0; st < 2; st++) {
            #pragma unroll
            for (int i = 0; i < 4; i++) {
                int cc  = i * 256 + tid;       // 0..1023
                int isV = cc >> 9;
                int r   = (cc >> 3) & 63;
                int c   = cc & 7;
                const __half* src = (isV ? Vg : Kg) + (st * BN + r) * DH + c * 8;
                __half* dst = (isV ? Vs[st] : Ks[st]) + r * KPAD + c * 8;
                cp16(dst, src);
            }
            asm volatile("cp.async.commit_group;\n");
        }
    }

    // --- load Q fragments straight from global (overlaps with cp.async) ---
    unsigned qa[4][4];
    {
        const __half* qrow0 = Qg + (q0 + w * 16 + gid) * DH;
        const __half* qrow1 = qrow0 + 8 * DH;
        #pragma unroll
        for (int kk = 0; kk < 4; kk++) {
            int c0 = kk * 16 + tig * 2;
            qa[kk][0] = *(const unsigned*)(qrow0 + c0);       // (gid,    c)
            qa[kk][1] = *(const unsigned*)(qrow1 + c0);       // (gid+8,  c)
            qa[kk][2] = *(const unsigned*)(qrow0 + c0 + 8);   // (gid,    c+8)
            qa[kk][3] = *(const unsigned*)(qrow1 + c0 + 8);   // (gid+8,  c+8)
        }
    }

    float o[8][4];
    #pragma unroll
    for (int j = 0; j < 8; j++) { o[j][0] = 0.f; o[j][1] = 0.f; o[j][2] = 0.f; o[j][3] = 0.f; }
    float m0 = -CUDART_INF_F, m1 = -CUDART_INF_F;
    float l0 = 0.f, l1 = 0.f;

    for (int t = 0; t < NTILES; t++) {
        const int st = t & 1;
        if (t + 1 < NTILES) asm volatile("cp.async.wait_group 1;\n");
        else                asm volatile("cp.async.wait_group 0;\n");
        __syncthreads();

        // ---- S = Q K^T (per-warp 16x64 tile) ----
        float s[8][4];
        #pragma unroll
        for (int j = 0; j < 8; j++) { s[j][0] = 0.f; s[j][1] = 0.f; s[j][2] = 0.f; s[j][3] = 0.f; }

        const __half* ks = Ks[st];
        #pragma unroll
        for (int j = 0; j < 8; j++) {
            #pragma unroll
            for (int kk2 = 0; kk2 < 2; kk2++) {
                unsigned b0, b1, b2, b3;
                const __half* p = ks + (j * 8 + (lane & 7)) * KPAD + kk2 * 32 + (lane >> 3) * 8;
                ldsm_x4(b0, b1, b2, b3, p);
                mma16816(s[j], qa[2 * kk2],     b0, b1);
                mma16816(s[j], qa[2 * kk2 + 1], b2, b3);
            }
        }

        // ---- online softmax (base-2 domain; Q pre-scaled by scale*log2e) ----
        float rm0 = -CUDART_INF_F, rm1 = -CUDART_INF_F;
        #pragma unroll
        for (int j = 0; j < 8; j++) {
            rm0 = fmaxf(rm0, fmaxf(s[j][0], s[j][1]));
            rm1 = fmaxf(rm1, fmaxf(s[j][2], s[j][3]));
        }
        rm0 = fmaxf(rm0, __shfl_xor_sync(0xffffffffu, rm0, 1));
        rm0 = fmaxf(rm0, __shfl_xor_sync(0xffffffffu, rm0, 2));
        rm1 = fmaxf(rm1, __shfl_xor_sync(0xffffffffu, rm1, 1));
        rm1 = fmaxf(rm1, __shfl_xor_sync(0xffffffffu, rm1, 2));

        float mn0 = fmaxf(m0, rm0), mn1 = fmaxf(m1, rm1);
        float a0 = fast_exp2(m0 - mn0), a1 = fast_exp2(m1 - mn1);
        m0 = mn0; m1 = mn1;

        float rs0 = 0.f, rs1 = 0.f;
        #pragma unroll
        for (int j = 0; j < 8; j++) {
            s[j][0] = fast_exp2(s[j][0] - m0);
            s[j][1] = fast_exp2(s[j][1] - m0);
            s[j][2] = fast_exp2(s[j][2] - m1);
            s[j][3] = fast_exp2(s[j][3] - m1);
            rs0 += s[j][0] + s[j][1];
            rs1 += s[j][2] + s[j][3];
        }
        rs0 += __shfl_xor_sync(0xffffffffu, rs0, 1);
        rs0 += __shfl_xor_sync(0xffffffffu, rs0, 2);
        rs1 += __shfl_xor_sync(0xffffffffu, rs1, 1);
        rs1 += __shfl_xor_sync(0xffffffffu, rs1, 2);
        l0 = l0 * a0 + rs0;
        l1 = l1 * a1 + rs1;

        #pragma unroll
        for (int j = 0; j < 8; j++) {
            o[j][0] *= a0; o[j][1] *= a0;
            o[j][2] *= a1; o[j][3] *= a1;
        }

        // pack P into A-fragments (key dim = k of PV mma)
        unsigned pa[4][4];
        #pragma unroll
        for (int kk = 0; kk < 4; kk++) {
            pa[kk][0] = pack_h2(s[2 * kk][0],     s[2 * kk][1]);
            pa[kk][1] = pack_h2(s[2 * kk][2],     s[2 * kk][3]);
            pa[kk][2] = pack_h2(s[2 * kk + 1][0], s[2 * kk + 1][1]);
            pa[kk][3] = pack_h2(s[2 * kk + 1][2], s[2 * kk + 1][3]);
        }

        // ---- O += P V ----
        const __half* vs = Vs[st];
        #pragma unroll
        for (int jd = 0; jd < 8; jd++) {
            #pragma unroll
            for (int kk2 = 0; kk2 < 2; kk2++) {
                unsigned b0, b1, b2, b3;
                const __half* p = vs + (kk2 * 32 + lane) * KPAD + jd * 8;
                ldsm_x4_t(b0, b1, b2, b3, p);
                mma16816(o[jd], pa[2 * kk2],     b0, b1);
                mma16816(o[jd], pa[2 * kk2 + 1], b2, b3);
            }
        }

        __syncthreads();

        // prefetch tile t+2 into the stage we just finished reading
        if (t + 2 < NTILES) {
            #pragma unroll
            for (int i = 0; i < 4; i++) {
                int cc  = i * 256 + tid;
                int isV = cc >> 9;
                int r   = (cc >> 3) & 63;
                int c   = cc & 7;
                const __half* src = (isV ? Vg : Kg) + ((t + 2) * BN + r) * DH + c * 8;
                __half* dst = (isV ? Vs[st] : Ks[st]) + r * KPAD + c * 8;
                cp16(dst, src);
            }
            asm volatile("cp.async.commit_group;\n");
        }
    }

    // ---- epilogue: normalize + output affine, direct stores ----
    float inv0 = 1.f / l0, inv1 = 1.f / l1;
    int row0 = q0 + w * 16 + gid;
    float* out0 = out + (b * SEQ + row0) * 256 + h * 64;
    float* out1 = out0 + 8 * 256;
    #pragma unroll
    for (int jd = 0; jd < 8; jd++) {
        int c = jd * 8 + tig * 2;
        float2 w2 = *(const float2*)(wp + h * 64 + c);
        float2 b2 = *(const float2*)(bp + h * 64 + c);
        float2 r0, r1;
        r0.x = o[jd][0] * inv0 * w2.x + b2.x;
        r0.y = o[jd][1] * inv0 * w2.y + b2.y;
        r1.x = o[jd][2] * inv1 * w2.x + b2.x;
        r1.y = o[jd][3] * inv1 * w2.y + b2.y;
        *(float2*)(out0 + c) = r0;
        *(float2*)(out1 + c) = r1;
    }
}

// ---------------- launch ----------------
extern "C" void kernel_launch(void* const* d_in, const int* in_sizes, int n_in,
                              void* d_out, int out_size)
{
    const float* q_in = (const float*)d_in[0];
    const float* k_in = (const float*)d_in[1];
    const float* v_in = (const float*)d_in[2];
    const float* wq = (const float*)d_in[3];
    const float* bq = (const float*)d_in[4];
    const float* wk = (const float*)d_in[5];
    const float* bk = (const float*)d_in[6];
    const float* wv = (const float*)d_in[7];
    const float* bv = (const float*)d_in[8];
    const float* wp = (const float*)d_in[9];
    const float* bp = (const float*)d_in[10];

    int B = in_sizes[0] / (SEQ * 256);   // expected 4
    int total4 = B * SEQ * 64;

    preprocess_kernel<<<(total4 + 255) / 256, 256>>>(
        q_in, k_in, v_in, wq, bq, wk, bk, wv, bv, total4);

    dim3 grid(SEQ / BM, B * NH);
    attn_kernel<<<grid, 256>>>((float*)d_out, wp, bp);
}

// round 2
// speedup vs baseline: 1.0391x; 1.0391x over previous
#include <cuda_runtime.h>
#include <cuda_fp16.h>
#include <math_constants.h>

#define SEQ 4096
#define DH 64
#define NH 4
#define BM 128
#define BN 64
#define NTILES (SEQ / BN)   // 64
#define KPAD 72             // padded half stride (144B) -> conflict-free ldmatrix
#define TSZ (BN * KPAD)     // halves per stage
#define STAGE_B (TSZ * 2)   // bytes per stage
#define SMEM_BYTES (8 * STAGE_B)  // 4 K stages + 4 V stages = 73728 B

// scratch: fp16 Q/K/V in (b,h,s,d) layout, affine applied (Q pre-scaled by scale*log2e)
__device__ __half g_Q[4 * NH * SEQ * DH];
__device__ __half g_K[4 * NH * SEQ * DH];
__device__ __half g_V[4 * NH * SEQ * DH];

__device__ __forceinline__ float fast_exp2(float x) {
    float y;
    asm("ex2.approx.f32 %0, %1;" : "=f"(y) : "f"(x));
    return y;
}

__device__ __forceinline__ unsigned pack_h2(float a, float b) {
    __half2 h = __floats2half2_rn(a, b);
    return *reinterpret_cast<unsigned*>(&h);
}

__device__ __forceinline__ unsigned ex2h2(unsigned x) {
    unsigned y;
    asm("ex2.approx.f16x2 %0, %1;" : "=r"(y) : "r"(x));
    return y;
}

// ---------------- preprocess: affine + fp16 + (b,h,s,d) reshape ----------------
__global__ void preprocess_kernel(
    const float* __restrict__ q_in, const float* __restrict__ k_in, const float* __restrict__ v_in,
    const float* __restrict__ wq, const float* __restrict__ bq,
    const float* __restrict__ wk, const float* __restrict__ bk,
    const float* __restrict__ wv, const float* __restrict__ bv,
    int total4)
{
    const float qs = 0.125f * 1.44269504088896340736f;  // d^-0.5 * log2(e)
    int i4 = blockIdx.x * blockDim.x + threadIdx.x;
    if (i4 >= total4) return;
    int c4 = i4 & 63;
    int s  = (i4 >> 6) & (SEQ - 1);
    int b  = i4 >> 18;
    int c  = c4 * 4;
    int h  = c >> 6;
    int d  = c & 63;
    int in_idx  = (b * SEQ + s) * 256 + c;
    int out_idx = ((b * NH + h) * SEQ + s) * DH + d;

    float4 qv = *(const float4*)(q_in + in_idx);
    float4 kv = *(const float4*)(k_in + in_idx);
    float4 vv = *(const float4*)(v_in + in_idx);

    float4 w, bb;
    uint2 p;

    w = *(const float4*)(wq + c); bb = *(const float4*)(bq + c);
    p.x = pack_h2((qv.x * w.x + bb.x) * qs, (qv.y * w.y + bb.y) * qs);
    p.y = pack_h2((qv.z * w.z + bb.z) * qs, (qv.w * w.w + bb.w) * qs);
    *(uint2*)(g_Q + out_idx) = p;

    w = *(const float4*)(wk + c); bb = *(const float4*)(bk + c);
    p.x = pack_h2(kv.x * w.x + bb.x, kv.y * w.y + bb.y);
    p.y = pack_h2(kv.z * w.z + bb.z, kv.w * w.w + bb.w);
    *(uint2*)(g_K + out_idx) = p;

    w = *(const float4*)(wv + c); bb = *(const float4*)(bv + c);
    p.x = pack_h2(vv.x * w.x + bb.x, vv.y * w.y + bb.y);
    p.y = pack_h2(vv.z * w.z + bb.z, vv.w * w.w + bb.w);
    *(uint2*)(g_V + out_idx) = p;
}

// ---------------- flash attention ----------------
__device__ __forceinline__ void mma16816(float c[4], const unsigned a[4], unsigned b0, unsigned b1) {
    asm volatile(
        "mma.sync.aligned.m16n8k16.row.col.f32.f16.f16.f32 "
        "{%0,%1,%2,%3},{%4,%5,%6,%7},{%8,%9},{%0,%1,%2,%3};\n"
        : "+f"(c[0]), "+f"(c[1]), "+f"(c[2]), "+f"(c[3])
        : "r"(a[0]), "r"(a[1]), "r"(a[2]), "r"(a[3]), "r"(b0), "r"(b1));
}

__device__ __forceinline__ void ldsm_x4u(unsigned& r0, unsigned& r1, unsigned& r2, unsigned& r3, unsigned addr) {
    asm volatile("ldmatrix.sync.aligned.m8n8.x4.shared.b16 {%0,%1,%2,%3}, [%4];\n"
                 : "=r"(r0), "=r"(r1), "=r"(r2), "=r"(r3) : "r"(addr));
}

__device__ __forceinline__ void ldsm_x4tu(unsigned& r0, unsigned& r1, unsigned& r2, unsigned& r3, unsigned addr) {
    asm volatile("ldmatrix.sync.aligned.m8n8.x4.trans.shared.b16 {%0,%1,%2,%3}, [%4];\n"
                 : "=r"(r0), "=r"(r1), "=r"(r2), "=r"(r3) : "r"(addr));
}

__device__ __forceinline__ void cp16u(unsigned dst, const __half* src) {
    asm volatile("cp.async.cg.shared.global [%0], [%1], 16;\n" :: "r"(dst), "l"(src));
}

__global__ void __launch_bounds__(256, 2) attn_kernel(
    float* __restrict__ out, const float* __restrict__ wp, const float* __restrict__ bp)
{
    extern __shared__ __half smbuf[];
    __half* Ks = smbuf;              // 4 stages
    __half* Vs = smbuf + 4 * TSZ;    // 4 stages
    const unsigned ks_u = (unsigned)__cvta_generic_to_shared(Ks);
    const unsigned vs_u = (unsigned)__cvta_generic_to_shared(Vs);

    const int tid  = threadIdx.x;
    const int w    = tid >> 5;
    const int lane = tid & 31;
    const int gid  = lane >> 2;   // 0..7
    const int tig  = lane & 3;    // 0..3

    const int bh = blockIdx.y;           // b*NH + h
    const int b  = bh >> 2;
    const int h  = bh & 3;
    const int q0 = blockIdx.x * BM;

    const __half* Qg = g_Q + bh * (SEQ * DH);
    const __half* Kg = g_K + bh * (SEQ * DH);
    const __half* Vg = g_V + bh * (SEQ * DH);

    // per-lane smem base offsets (bytes) for ldmatrix
    const unsigned kbase = ks_u + ((lane & 7) * KPAD + (lane >> 3) * 8) * 2;
    const unsigned vbase = vs_u + (lane * KPAD) * 2;

    // ---- fill lambdas (2 cp.async.16 per thread per tile) ----
    auto fillK = [&](int f) {
        if (f >= NTILES) return;
        unsigned dst0 = ks_u + (f & 3) * STAGE_B;
        const __half* src = Kg + f * BN * DH;
        #pragma unroll
        for (int i = 0; i < 2; i++) {
            int idx = i * 256 + tid;
            int r = idx >> 3, c = idx & 7;
            cp16u(dst0 + (r * KPAD + c * 8) * 2, src + r * DH + c * 8);
        }
    };
    auto fillV = [&](int f) {
        if (f >= NTILES) return;
        unsigned dst0 = vs_u + (f & 3) * STAGE_B;
        const __half* src = Vg + f * BN * DH;
        #pragma unroll
        for (int i = 0; i < 2; i++) {
            int idx = i * 256 + tid;
            int r = idx >> 3, c = idx & 7;
            cp16u(dst0 + (r * KPAD + c * 8) * 2, src + r * DH + c * 8);
        }
    };

    // prologue: 3 commit groups
    fillK(0); fillV(0); asm volatile("cp.async.commit_group;\n");
    fillK(1); fillV(1); asm volatile("cp.async.commit_group;\n");
    fillK(2);           asm volatile("cp.async.commit_group;\n");

    // ---- Q fragments from global (overlaps with cp.async) ----
    unsigned qa[4][4];
    {
        const __half* qrow0 = Qg + (q0 + w * 16 + gid) * DH;
        const __half* qrow1 = qrow0 + 8 * DH;
        #pragma unroll
        for (int kk = 0; kk < 4; kk++) {
            int c0 = kk * 16 + tig * 2;
            qa[kk][0] = *(const unsigned*)(qrow0 + c0);
            qa[kk][1] = *(const unsigned*)(qrow1 + c0);
            qa[kk][2] = *(const unsigned*)(qrow0 + c0 + 8);
            qa[kk][3] = *(const unsigned*)(qrow1 + c0 + 8);
        }
    }

    float o[8][4];
    #pragma unroll
    for (int j = 0; j < 8; j++) { o[j][0] = 0.f; o[j][1] = 0.f; o[j][2] = 0.f; o[j][3] = 0.f; }
    float m0 = -CUDART_INF_F, m1 = -CUDART_INF_F;
    float l0 = 0.f, l1 = 0.f;

    unsigned paA[4][4], paB[4][4];

    // PV of tile tp using fragments pr, accumulating into o
    auto pv = [&](int tp, const unsigned (&pr)[4][4]) {
        const unsigned vst = vbase + (tp & 3) * STAGE_B;
        #pragma unroll
        for (int jd = 0; jd < 8; jd++) {
            #pragma unroll
            for (int kk2 = 0; kk2 < 2; kk2++) {
                unsigned b0, b1, b2, b3;
                ldsm_x4tu(b0, b1, b2, b3, vst + kk2 * (32 * KPAD * 2) + jd * 16);
                mma16816(o[jd], pr[2 * kk2],     b0, b1);
                mma16816(o[jd], pr[2 * kk2 + 1], b2, b3);
            }
        }
    };

    // one tile body: wait/barrier/prefetch, S=QK(t), softmax -> pw, PV(t-1) with pr, rescale
    auto body = [&](int t, const unsigned (&pr)[4][4], unsigned (&pw)[4][4], bool doPV) {
        asm volatile("cp.async.wait_group 2;\n");
        __syncthreads();
        fillK(t + 3);
        fillV(t + 2);
        asm volatile("cp.async.commit_group;\n");

        // ---- S = Q K^T ----
        float s[8][4];
        #pragma unroll
        for (int j = 0; j < 8; j++) { s[j][0] = 0.f; s[j][1] = 0.f; s[j][2] = 0.f; s[j][3] = 0.f; }
        const unsigned kst = kbase + (t & 3) * STAGE_B;
        #pragma unroll
        for (int j = 0; j < 8; j++) {
            #pragma unroll
            for (int kk2 = 0; kk2 < 2; kk2++) {
                unsigned b0, b1, b2, b3;
                ldsm_x4u(b0, b1, b2, b3, kst + j * (8 * KPAD * 2) + kk2 * 64);
                mma16816(s[j], qa[2 * kk2],     b0, b1);
                mma16816(s[j], qa[2 * kk2 + 1], b2, b3);
            }
        }

        // ---- softmax part 1: row max ----
        float rm0 = -CUDART_INF_F, rm1 = -CUDART_INF_F;
        #pragma unroll
        for (int j = 0; j < 8; j++) {
            rm0 = fmaxf(rm0, fmaxf(s[j][0], s[j][1]));
            rm1 = fmaxf(rm1, fmaxf(s[j][2], s[j][3]));
        }
        rm0 = fmaxf(rm0, __shfl_xor_sync(0xffffffffu, rm0, 1));
        rm0 = fmaxf(rm0, __shfl_xor_sync(0xffffffffu, rm0, 2));
        rm1 = fmaxf(rm1, __shfl_xor_sync(0xffffffffu, rm1, 1));
        rm1 = fmaxf(rm1, __shfl_xor_sync(0xffffffffu, rm1, 2));

        float mn0 = fmaxf(m0, rm0), mn1 = fmaxf(m1, rm1);
        float a0 = fast_exp2(m0 - mn0), a1 = fast_exp2(m1 - mn1);

        // ---- exponentials in fp16x2: result IS the mma A-fragment ----
        #pragma unroll
        for (int kk = 0; kk < 4; kk++) {
            pw[kk][0] = ex2h2(pack_h2(s[2 * kk][0] - mn0,     s[2 * kk][1] - mn0));
            pw[kk][1] = ex2h2(pack_h2(s[2 * kk][2] - mn1,     s[2 * kk][3] - mn1));
            pw[kk][2] = ex2h2(pack_h2(s[2 * kk + 1][0] - mn0, s[2 * kk + 1][1] - mn0));
            pw[kk][3] = ex2h2(pack_h2(s[2 * kk + 1][2] - mn1, s[2 * kk + 1][3] - mn1));
        }

        // row sums (fp32 accumulation from half2 exps)
        float rs0 = 0.f, rs1 = 0.f;
        #pragma unroll
        for (int kk = 0; kk < 4; kk++) {
            float2 f0 = __half22float2(*reinterpret_cast<const __half2*>(&pw[kk][0]));
            float2 f2 = __half22float2(*reinterpret_cast<const __half2*>(&pw[kk][2]));
            rs0 += (f0.x + f0.y) + (f2.x + f2.y);
            float2 f1 = __half22float2(*reinterpret_cast<const __half2*>(&pw[kk][1]));
            float2 f3 = __half22float2(*reinterpret_cast<const __half2*>(&pw[kk][3]));
            rs1 += (f1.x + f1.y) + (f3.x + f3.y);
        }
        rs0 += __shfl_xor_sync(0xffffffffu, rs0, 1);
        rs0 += __shfl_xor_sync(0xffffffffu, rs0, 2);
        rs1 += __shfl_xor_sync(0xffffffffu, rs1, 1);
        rs1 += __shfl_xor_sync(0xffffffffu, rs1, 2);

        // ---- deferred PV of previous tile (independent of softmax above:
        // HW/compiler overlaps MUFU chain with these HMMA/ldsm) ----
        if (doPV) pv(t - 1, pr);

        // ---- state update (must follow PV: o holds old-scale accumulation) ----
        #pragma unroll
        for (int j = 0; j < 8; j++) {
            o[j][0] *= a0; o[j][1] *= a0;
            o[j][2] *= a1; o[j][3] *= a1;
        }
        l0 = l0 * a0 + rs0;
        l1 = l1 * a1 + rs1;
        m0 = mn0; m1 = mn1;
    };

    // peel t=0 (writes paA), t=1 (paA -> paB), then pairs keep parity static
    body(0, paA, paA, false);
    body(1, paA, paB, true);
    #pragma unroll 1
    for (int t = 2; t < NTILES; t += 2) {
        body(t,     paB, paA, true);
        body(t + 1, paA, paB, true);
    }
    // final PV for tile 63 (fragments in paB, V stage 3 still resident)
    pv(NTILES - 1, paB);

    // ---- epilogue: normalize + output affine, direct stores ----
    float inv0 = 1.f / l0, inv1 = 1.f / l1;
    int row0 = q0 + w * 16 + gid;
    float* out0 = out + (b * SEQ + row0) * 256 + h * 64;
    float* out1 = out0 + 8 * 256;
    #pragma unroll
    for (int jd = 0; jd < 8; jd++) {
        int c = jd * 8 + tig * 2;
        float2 w2 = *(const float2*)(wp + h * 64 + c);
        float2 b2 = *(const float2*)(bp + h * 64 + c);
        float2 r0, r1;
        r0.x = o[jd][0] * inv0 * w2.x + b2.x;
        r0.y = o[jd][1] * inv0 * w2.y + b2.y;
        r1.x = o[jd][2] * inv1 * w2.x + b2.x;
        r1.y = o[jd][3] * inv1 * w2.y + b2.y;
        *(float2*)(out0 + c) = r0;
        *(float2*)(out1 + c) = r1;
    }
}

// ---------------- launch ----------------
extern "C" void kernel_launch(void* const* d_in, const int* in_sizes, int n_in,
                              void* d_out, int out_size)
{
    const float* q_in = (const float*)d_in[0];
    const float* k_in = (const float*)d_in[1];
    const float* v_in = (const float*)d_in[2];
    const float* wq = (const float*)d_in[3];
    const float* bq = (const float*)d_in[4];
    const float* wk = (const float*)d_in[5];
    const float* bk = (const float*)d_in[6];
    const float* wv = (const float*)d_in[7];
    const float* bv = (const float*)d_in[8];
    const float* wp = (const float*)d_in[9];
    const float* bp = (const float*)d_in[10];

    int B = in_sizes[0] / (SEQ * 256);   // expected 4
    int total4 = B * SEQ * 64;

    cudaFuncSetAttribute(attn_kernel, cudaFuncAttributeMaxDynamicSharedMemorySize, SMEM_BYTES);

    preprocess_kernel<<<(total4 + 255) / 256, 256>>>(
        q_in, k_in, v_in, wq, bq, wk, bk, wv, bv, total4);

    dim3 grid(SEQ / BM, B * NH);
    attn_kernel<<<grid, 256, SMEM_BYTES>>>((float*)d_out, wp, bp);
}

// round 3
// speedup vs baseline: 1.0394x; 1.0004x over previous
#include <cuda_runtime.h>
#include <cuda_fp16.h>
#include <math_constants.h>

#define SEQ 4096
#define DH 64
#define NH 4
#define BM 128
#define BN 64
#define NTILES (SEQ / BN)   // 64
#define KPAD 72             // padded half stride (144B) -> conflict-free ldmatrix
#define TSZ (BN * KPAD)     // halves per stage
#define STAGE_B (TSZ * 2)   // bytes per stage
#define SMEM_BYTES (8 * STAGE_B)  // 4 K stages + 4 V stages = 73728 B

// scratch: fp16 Q/K/V in (b,h,s,d) layout, affine applied (Q pre-scaled by scale*log2e)
__device__ __half g_Q[4 * NH * SEQ * DH];
__device__ __half g_K[4 * NH * SEQ * DH];
__device__ __half g_V[4 * NH * SEQ * DH];

__device__ __forceinline__ float fast_exp2(float x) {
    float y;
    asm("ex2.approx.f32 %0, %1;" : "=f"(y) : "f"(x));
    return y;
}

__device__ __forceinline__ unsigned pack_h2(float a, float b) {
    __half2 h = __floats2half2_rn(a, b);
    return *reinterpret_cast<unsigned*>(&h);
}

__device__ __forceinline__ unsigned ex2h2(unsigned x) {
    unsigned y;
    asm("ex2.approx.f16x2 %0, %1;" : "=r"(y) : "r"(x));
    return y;
}

// ---------------- preprocess: affine + fp16 + (b,h,s,d) reshape ----------------
__global__ void preprocess_kernel(
    const float* __restrict__ q_in, const float* __restrict__ k_in, const float* __restrict__ v_in,
    const float* __restrict__ wq, const float* __restrict__ bq,
    const float* __restrict__ wk, const float* __restrict__ bk,
    const float* __restrict__ wv, const float* __restrict__ bv,
    int total4)
{
    const float qs = 0.125f * 1.44269504088896340736f;  // d^-0.5 * log2(e)
    int i4 = blockIdx.x * blockDim.x + threadIdx.x;
    if (i4 >= total4) return;
    int c4 = i4 & 63;
    int s  = (i4 >> 6) & (SEQ - 1);
    int b  = i4 >> 18;
    int c  = c4 * 4;
    int h  = c >> 6;
    int d  = c & 63;
    int in_idx  = (b * SEQ + s) * 256 + c;
    int out_idx = ((b * NH + h) * SEQ + s) * DH + d;

    float4 qv = *(const float4*)(q_in + in_idx);
    float4 kv = *(const float4*)(k_in + in_idx);
    float4 vv = *(const float4*)(v_in + in_idx);

    float4 w, bb;
    uint2 p;

    w = *(const float4*)(wq + c); bb = *(const float4*)(bq + c);
    p.x = pack_h2((qv.x * w.x + bb.x) * qs, (qv.y * w.y + bb.y) * qs);
    p.y = pack_h2((qv.z * w.z + bb.z) * qs, (qv.w * w.w + bb.w) * qs);
    *(uint2*)(g_Q + out_idx) = p;

    w = *(const float4*)(wk + c); bb = *(const float4*)(bk + c);
    p.x = pack_h2(kv.x * w.x + bb.x, kv.y * w.y + bb.y);
    p.y = pack_h2(kv.z * w.z + bb.z, kv.w * w.w + bb.w);
    *(uint2*)(g_K + out_idx) = p;

    w = *(const float4*)(wv + c); bb = *(const float4*)(bv + c);
    p.x = pack_h2(vv.x * w.x + bb.x, vv.y * w.y + bb.y);
    p.y = pack_h2(vv.z * w.z + bb.z, vv.w * w.w + bb.w);
    *(uint2*)(g_V + out_idx) = p;
}

// ---------------- flash attention ----------------
__device__ __forceinline__ void mma16816(float c[4], const unsigned a[4], unsigned b0, unsigned b1) {
    asm volatile(
        "mma.sync.aligned.m16n8k16.row.col.f32.f16.f16.f32 "
        "{%0,%1,%2,%3},{%4,%5,%6,%7},{%8,%9},{%0,%1,%2,%3};\n"
        : "+f"(c[0]), "+f"(c[1]), "+f"(c[2]), "+f"(c[3])
        : "r"(a[0]), "r"(a[1]), "r"(a[2]), "r"(a[3]), "r"(b0), "r"(b1));
}

__device__ __forceinline__ void ldsm_x4u(unsigned& r0, unsigned& r1, unsigned& r2, unsigned& r3, unsigned addr) {
    asm volatile("ldmatrix.sync.aligned.m8n8.x4.shared.b16 {%0,%1,%2,%3}, [%4];\n"
                 : "=r"(r0), "=r"(r1), "=r"(r2), "=r"(r3) : "r"(addr));
}

__device__ __forceinline__ void ldsm_x4tu(unsigned& r0, unsigned& r1, unsigned& r2, unsigned& r3, unsigned addr) {
    asm volatile("ldmatrix.sync.aligned.m8n8.x4.trans.shared.b16 {%0,%1,%2,%3}, [%4];\n"
                 : "=r"(r0), "=r"(r1), "=r"(r2), "=r"(r3) : "r"(addr));
}

__device__ __forceinline__ void cp16u(unsigned dst, const __half* src) {
    asm volatile("cp.async.cg.shared.global [%0], [%1], 16;\n" :: "r"(dst), "l"(src));
}

__global__ void __launch_bounds__(256, 2) attn_kernel(
    float* __restrict__ out, const float* __restrict__ wp, const float* __restrict__ bp)
{
    extern __shared__ __half smbuf[];
    __half* Ks = smbuf;              // 4 stages
    __half* Vs = smbuf + 4 * TSZ;    // 4 stages
    const unsigned ks_u = (unsigned)__cvta_generic_to_shared(Ks);
    const unsigned vs_u = (unsigned)__cvta_generic_to_shared(Vs);

    const int tid  = threadIdx.x;
    const int w    = tid >> 5;
    const int lane = tid & 31;
    const int gid  = lane >> 2;   // 0..7
    const int tig  = lane & 3;    // 0..3

    const int bh = blockIdx.y;           // b*NH + h
    const int b  = bh >> 2;
    const int h  = bh & 3;
    const int q0 = blockIdx.x * BM;

    const __half* Qg = g_Q + bh * (SEQ * DH);
    const __half* Kg = g_K + bh * (SEQ * DH);
    const __half* Vg = g_V + bh * (SEQ * DH);

    // per-lane smem base offsets (bytes) for ldmatrix
    const unsigned kbase = ks_u + ((lane & 7) * KPAD + (lane >> 3) * 8) * 2;
    const unsigned vbase = vs_u + (lane * KPAD) * 2;

    // ---- fill lambdas (2 cp.async.16 per thread per tile) ----
    auto fillK = [&](int f) {
        if (f >= NTILES) return;
        unsigned dst0 = ks_u + (f & 3) * STAGE_B;
        const __half* src = Kg + f * BN * DH;
        #pragma unroll
        for (int i = 0; i < 2; i++) {
            int idx = i * 256 + tid;
            int r = idx >> 3, c = idx & 7;
            cp16u(dst0 + (r * KPAD + c * 8) * 2, src + r * DH + c * 8);
        }
    };
    auto fillV = [&](int f) {
        if (f >= NTILES) return;
        unsigned dst0 = vs_u + (f & 3) * STAGE_B;
        const __half* src = Vg + f * BN * DH;
        #pragma unroll
        for (int i = 0; i < 2; i++) {
            int idx = i * 256 + tid;
            int r = idx >> 3, c = idx & 7;
            cp16u(dst0 + (r * KPAD + c * 8) * 2, src + r * DH + c * 8);
        }
    };

    // prologue: 3 commit groups
    fillK(0); fillV(0); asm volatile("cp.async.commit_group;\n");
    fillK(1); fillV(1); asm volatile("cp.async.commit_group;\n");
    fillK(2);           asm volatile("cp.async.commit_group;\n");

    // ---- Q fragments from global (overlaps with cp.async) ----
    unsigned qa[4][4];
    {
        const __half* qrow0 = Qg + (q0 + w * 16 + gid) * DH;
        const __half* qrow1 = qrow0 + 8 * DH;
        #pragma unroll
        for (int kk = 0; kk < 4; kk++) {
            int c0 = kk * 16 + tig * 2;
            qa[kk][0] = *(const unsigned*)(qrow0 + c0);
            qa[kk][1] = *(const unsigned*)(qrow1 + c0);
            qa[kk][2] = *(const unsigned*)(qrow0 + c0 + 8);
            qa[kk][3] = *(const unsigned*)(qrow1 + c0 + 8);
        }
    }

    float o[8][4];
    #pragma unroll
    for (int j = 0; j < 8; j++) { o[j][0] = 0.f; o[j][1] = 0.f; o[j][2] = 0.f; o[j][3] = 0.f; }
    float m0 = -CUDART_INF_F, m1 = -CUDART_INF_F;
    float l0 = 0.f, l1 = 0.f;

    unsigned paA[4][4], paB[4][4];

    // PV of tile tp using fragments pr, accumulating into o
    auto pv = [&](int tp, const unsigned (&pr)[4][4]) {
        const unsigned vst = vbase + (tp & 3) * STAGE_B;
        #pragma unroll
        for (int jd = 0; jd < 8; jd++) {
            #pragma unroll
            for (int kk2 = 0; kk2 < 2; kk2++) {
                unsigned b0, b1, b2, b3;
                ldsm_x4tu(b0, b1, b2, b3, vst + kk2 * (32 * KPAD * 2) + jd * 16);
                mma16816(o[jd], pr[2 * kk2],     b0, b1);
                mma16816(o[jd], pr[2 * kk2 + 1], b2, b3);
            }
        }
    };

    // one tile body: wait/barrier/prefetch, S=QK(t), softmax -> pw, PV(t-1) with pr, rescale
    auto body = [&](int t, const unsigned (&pr)[4][4], unsigned (&pw)[4][4], bool doPV) {
        asm volatile("cp.async.wait_group 2;\n");
        __syncthreads();
        fillK(t + 3);
        fillV(t + 2);
        asm volatile("cp.async.commit_group;\n");

        // ---- S = Q K^T ----
        float s[8][4];
        #pragma unroll
        for (int j = 0; j < 8; j++) { s[j][0] = 0.f; s[j][1] = 0.f; s[j][2] = 0.f; s[j][3] = 0.f; }
        const unsigned kst = kbase + (t & 3) * STAGE_B;
        #pragma unroll
        for (int j = 0; j < 8; j++) {
            #pragma unroll
            for (int kk2 = 0; kk2 < 2; kk2++) {
                unsigned b0, b1, b2, b3;
                ldsm_x4u(b0, b1, b2, b3, kst + j * (8 * KPAD * 2) + kk2 * 64);
                mma16816(s[j], qa[2 * kk2],     b0, b1);
                mma16816(s[j], qa[2 * kk2 + 1], b2, b3);
            }
        }

        // ---- softmax part 1: row max ----
        float rm0 = -CUDART_INF_F, rm1 = -CUDART_INF_F;
        #pragma unroll
        for (int j = 0; j < 8; j++) {
            rm0 = fmaxf(rm0, fmaxf(s[j][0], s[j][1]));
            rm1 = fmaxf(rm1, fmaxf(s[j][2], s[j][3]));
        }
        rm0 = fmaxf(rm0, __shfl_xor_sync(0xffffffffu, rm0, 1));
        rm0 = fmaxf(rm0, __shfl_xor_sync(0xffffffffu, rm0, 2));
        rm1 = fmaxf(rm1, __shfl_xor_sync(0xffffffffu, rm1, 1));
        rm1 = fmaxf(rm1, __shfl_xor_sync(0xffffffffu, rm1, 2));

        float mn0 = fmaxf(m0, rm0), mn1 = fmaxf(m1, rm1);
        float a0 = fast_exp2(m0 - mn0), a1 = fast_exp2(m1 - mn1);

        // ---- exponentials in fp16x2: result IS the mma A-fragment ----
        #pragma unroll
        for (int kk = 0; kk < 4; kk++) {
            pw[kk][0] = ex2h2(pack_h2(s[2 * kk][0] - mn0,     s[2 * kk][1] - mn0));
            pw[kk][1] = ex2h2(pack_h2(s[2 * kk][2] - mn1,     s[2 * kk][3] - mn1));
            pw[kk][2] = ex2h2(pack_h2(s[2 * kk + 1][0] - mn0, s[2 * kk + 1][1] - mn0));
            pw[kk][3] = ex2h2(pack_h2(s[2 * kk + 1][2] - mn1, s[2 * kk + 1][3] - mn1));
        }

        // row sums (fp32 accumulation from half2 exps)
        float rs0 = 0.f, rs1 = 0.f;
        #pragma unroll
        for (int kk = 0; kk < 4; kk++) {
            float2 f0 = __half22float2(*reinterpret_cast<const __half2*>(&pw[kk][0]));
            float2 f2 = __half22float2(*reinterpret_cast<const __half2*>(&pw[kk][2]));
            rs0 += (f0.x + f0.y) + (f2.x + f2.y);
            float2 f1 = __half22float2(*reinterpret_cast<const __half2*>(&pw[kk][1]));
            float2 f3 = __half22float2(*reinterpret_cast<const __half2*>(&pw[kk][3]));
            rs1 += (f1.x + f1.y) + (f3.x + f3.y);
        }
        rs0 += __shfl_xor_sync(0xffffffffu, rs0, 1);
        rs0 += __shfl_xor_sync(0xffffffffu, rs0, 2);
        rs1 += __shfl_xor_sync(0xffffffffu, rs1, 1);
        rs1 += __shfl_xor_sync(0xffffffffu, rs1, 2);

        // ---- deferred PV of previous tile (independent of softmax above:
        // HW/compiler overlaps MUFU chain with these HMMA/ldsm) ----
        if (doPV) pv(t - 1, pr);

        // ---- state update (must follow PV: o holds old-scale accumulation) ----
        #pragma unroll
        for (int j = 0; j < 8; j++) {
            o[j][0] *= a0; o[j][1] *= a0;
            o[j][2] *= a1; o[j][3] *= a1;
        }
        l0 = l0 * a0 + rs0;
        l1 = l1 * a1 + rs1;
        m0 = mn0; m1 = mn1;
    };

    // peel t=0 (writes paA), t=1 (paA -> paB), then pairs keep parity static
    body(0, paA, paA, false);
    body(1, paA, paB, true);
    #pragma unroll 1
    for (int t = 2; t < NTILES; t += 2) {
        body(t,     paB, paA, true);
        body(t + 1, paA, paB, true);
    }
    // final PV for tile 63 (fragments in paB, V stage 3 still resident)
    pv(NTILES - 1, paB);

    // ---- epilogue: normalize + output affine, direct stores ----
    float inv0 = 1.f / l0, inv1 = 1.f / l1;
    int row0 = q0 + w * 16 + gid;
    float* out0 = out + (b * SEQ + row0) * 256 + h * 64;
    float* out1 = out0 + 8 * 256;
    #pragma unroll
    for (int jd = 0; jd < 8; jd++) {
        int c = jd * 8 + tig * 2;
        float2 w2 = *(const float2*)(wp + h * 64 + c);
        float2 b2 = *(const float2*)(bp + h * 64 + c);
        float2 r0, r1;
        r0.x = o[jd][0] * inv0 * w2.x + b2.x;
        r0.y = o[jd][1] * inv0 * w2.y + b2.y;
        r1.x = o[jd][2] * inv1 * w2.x + b2.x;
        r1.y = o[jd][3] * inv1 * w2.y + b2.y;
        *(float2*)(out0 + c) = r0;
        *(float2*)(out1 + c) = r1;
    }
}

// ---------------- launch ----------------
extern "C" void kernel_launch(void* const* d_in, const int* in_sizes, int n_in,
                              void* d_out, int out_size)
{
    const float* q_in = (const float*)d_in[0];
    const float* k_in = (const float*)d_in[1];
    const float* v_in = (const float*)d_in[2];
    const float* wq = (const float*)d_in[3];
    const float* bq = (const float*)d_in[4];
    const float* wk = (const float*)d_in[5];
    const float* bk = (const float*)d_in[6];
    const float* wv = (const float*)d_in[7];
    const float* bv = (const float*)d_in[8];
    const float* wp = (const float*)d_in[9];
    const float* bp = (const float*)d_in[10];

    int B = in_sizes[0] / (SEQ * 256);   // expected 4
    int total4 = B * SEQ * 64;

    cudaFuncSetAttribute(attn_kernel, cudaFuncAttributeMaxDynamicSharedMemorySize, SMEM_BYTES);

    preprocess_kernel<<<(total4 + 255) / 256, 256>>>(
        q_in, k_in, v_in, wq, bq, wk, bk, wv, bv, total4);

    dim3 grid(SEQ / BM, B * NH);
    attn_kernel<<<grid, 256, SMEM_BYTES>>>((float*)d_out, wp, bp);
}

// round 4
// speedup vs baseline: 1.0406x; 1.0011x over previous
#include <cuda_runtime.h>
#include <cuda_fp16.h>
#include <math_constants.h>

#define SEQ 4096
#define DH 64
#define NH 4
#define BM 128
#define BN 64
#define NTILES (SEQ / BN)   // 64
#define KPAD 72             // padded half stride (144B) -> conflict-free ldmatrix
#define TSZ (BN * KPAD)     // halves per stage
#define STAGE_B (TSZ * 2)   // bytes per stage
#define SMEM_BYTES (8 * STAGE_B)  // 4 K stages + 4 V stages = 73728 B

// scratch: fp16 Q/K/V in (b,h,s,d) layout, affine applied (Q pre-scaled by scale*log2e)
__device__ __half g_Q[4 * NH * SEQ * DH];
__device__ __half g_K[4 * NH * SEQ * DH];
__device__ __half g_V[4 * NH * SEQ * DH];

__device__ __forceinline__ float fast_exp2(float x) {
    float y;
    asm("ex2.approx.f32 %0, %1;" : "=f"(y) : "f"(x));
    return y;
}

__device__ __forceinline__ unsigned pack_h2(float a, float b) {
    __half2 h = __floats2half2_rn(a, b);
    return *reinterpret_cast<unsigned*>(&h);
}

__device__ __forceinline__ unsigned ex2h2(unsigned x) {
    unsigned y;
    asm("ex2.approx.f16x2 %0, %1;" : "=r"(y) : "r"(x));
    return y;
}

// ---------------- preprocess: affine + fp16 + (b,h,s,d) reshape ----------------
__global__ void preprocess_kernel(
    const float* __restrict__ q_in, const float* __restrict__ k_in, const float* __restrict__ v_in,
    const float* __restrict__ wq, const float* __restrict__ bq,
    const float* __restrict__ wk, const float* __restrict__ bk,
    const float* __restrict__ wv, const float* __restrict__ bv,
    int total4)
{
    const float qs = 0.125f * 1.44269504088896340736f;  // d^-0.5 * log2(e)
    int i4 = blockIdx.x * blockDim.x + threadIdx.x;
    if (i4 >= total4) return;
    int c4 = i4 & 63;
    int s  = (i4 >> 6) & (SEQ - 1);
    int b  = i4 >> 18;
    int c  = c4 * 4;
    int h  = c >> 6;
    int d  = c & 63;
    int in_idx  = (b * SEQ + s) * 256 + c;
    int out_idx = ((b * NH + h) * SEQ + s) * DH + d;

    float4 qv = *(const float4*)(q_in + in_idx);
    float4 kv = *(const float4*)(k_in + in_idx);
    float4 vv = *(const float4*)(v_in + in_idx);

    float4 w, bb;
    uint2 p;

    w = *(const float4*)(wq + c); bb = *(const float4*)(bq + c);
    p.x = pack_h2((qv.x * w.x + bb.x) * qs, (qv.y * w.y + bb.y) * qs);
    p.y = pack_h2((qv.z * w.z + bb.z) * qs, (qv.w * w.w + bb.w) * qs);
    *(uint2*)(g_Q + out_idx) = p;

    w = *(const float4*)(wk + c); bb = *(const float4*)(bk + c);
    p.x = pack_h2(kv.x * w.x + bb.x, kv.y * w.y + bb.y);
    p.y = pack_h2(kv.z * w.z + bb.z, kv.w * w.w + bb.w);
    *(uint2*)(g_K + out_idx) = p;

    w = *(const float4*)(wv + c); bb = *(const float4*)(bv + c);
    p.x = pack_h2(vv.x * w.x + bb.x, vv.y * w.y + bb.y);
    p.y = pack_h2(vv.z * w.z + bb.z, vv.w * w.w + bb.w);
    *(uint2*)(g_V + out_idx) = p;
}

// ---------------- flash attention ----------------
__device__ __forceinline__ void mma16816(float c[4], const unsigned a[4], unsigned b0, unsigned b1) {
    asm volatile(
        "mma.sync.aligned.m16n8k16.row.col.f32.f16.f16.f32 "
        "{%0,%1,%2,%3},{%4,%5,%6,%7},{%8,%9},{%0,%1,%2,%3};\n"
        : "+f"(c[0]), "+f"(c[1]), "+f"(c[2]), "+f"(c[3])
        : "r"(a[0]), "r"(a[1]), "r"(a[2]), "r"(a[3]), "r"(b0), "r"(b1));
}

__device__ __forceinline__ void ldsm_x4u(unsigned& r0, unsigned& r1, unsigned& r2, unsigned& r3, unsigned addr) {
    asm volatile("ldmatrix.sync.aligned.m8n8.x4.shared.b16 {%0,%1,%2,%3}, [%4];\n"
                 : "=r"(r0), "=r"(r1), "=r"(r2), "=r"(r3) : "r"(addr));
}

__device__ __forceinline__ void ldsm_x4tu(unsigned& r0, unsigned& r1, unsigned& r2, unsigned& r3, unsigned addr) {
    asm volatile("ldmatrix.sync.aligned.m8n8.x4.trans.shared.b16 {%0,%1,%2,%3}, [%4];\n"
                 : "=r"(r0), "=r"(r1), "=r"(r2), "=r"(r3) : "r"(addr));
}

__device__ __forceinline__ void cp16u(unsigned dst, const __half* src) {
    asm volatile("cp.async.cg.shared.global [%0], [%1], 16;\n" :: "r"(dst), "l"(src));
}

__global__ void __launch_bounds__(256, 2) attn_kernel(
    float* __restrict__ out, const float* __restrict__ wp, const float* __restrict__ bp)
{
    extern __shared__ __half smbuf[];
    __half* Ks = smbuf;              // 4 stages
    __half* Vs = smbuf + 4 * TSZ;    // 4 stages
    const unsigned ks_u = (unsigned)__cvta_generic_to_shared(Ks);
    const unsigned vs_u = (unsigned)__cvta_generic_to_shared(Vs);

    const int tid  = threadIdx.x;
    const int w    = tid >> 5;
    const int lane = tid & 31;
    const int gid  = lane >> 2;   // 0..7
    const int tig  = lane & 3;    // 0..3

    const int bh = blockIdx.y;           // b*NH + h
    const int b  = bh >> 2;
    const int h  = bh & 3;
    const int q0 = blockIdx.x * BM;

    const __half* Qg = g_Q + bh * (SEQ * DH);
    const __half* Kg = g_K + bh * (SEQ * DH);
    const __half* Vg = g_V + bh * (SEQ * DH);

    // per-lane smem base offsets (bytes) for ldmatrix
    const unsigned kbase = ks_u + ((lane & 7) * KPAD + (lane >> 3) * 8) * 2;
    const unsigned vbase = vs_u + (lane * KPAD) * 2;

    // ---- fill lambdas (2 cp.async.16 per thread per tile) ----
    auto fillK = [&](int f) {
        if (f >= NTILES) return;
        unsigned dst0 = ks_u + (f & 3) * STAGE_B;
        const __half* src = Kg + f * BN * DH;
        #pragma unroll
        for (int i = 0; i < 2; i++) {
            int idx = i * 256 + tid;
            int r = idx >> 3, c = idx & 7;
            cp16u(dst0 + (r * KPAD + c * 8) * 2, src + r * DH + c * 8);
        }
    };
    auto fillV = [&](int f) {
        if (f >= NTILES) return;
        unsigned dst0 = vs_u + (f & 3) * STAGE_B;
        const __half* src = Vg + f * BN * DH;
        #pragma unroll
        for (int i = 0; i < 2; i++) {
            int idx = i * 256 + tid;
            int r = idx >> 3, c = idx & 7;
            cp16u(dst0 + (r * KPAD + c * 8) * 2, src + r * DH + c * 8);
        }
    };

    // prologue: 3 commit groups
    fillK(0); fillV(0); asm volatile("cp.async.commit_group;\n");
    fillK(1); fillV(1); asm volatile("cp.async.commit_group;\n");
    fillK(2);           asm volatile("cp.async.commit_group;\n");

    // ---- Q fragments from global (overlaps with cp.async) ----
    unsigned qa[4][4];
    {
        const __half* qrow0 = Qg + (q0 + w * 16 + gid) * DH;
        const __half* qrow1 = qrow0 + 8 * DH;
        #pragma unroll
        for (int kk = 0; kk < 4; kk++) {
            int c0 = kk * 16 + tig * 2;
            qa[kk][0] = *(const unsigned*)(qrow0 + c0);
            qa[kk][1] = *(const unsigned*)(qrow1 + c0);
            qa[kk][2] = *(const unsigned*)(qrow0 + c0 + 8);
            qa[kk][3] = *(const unsigned*)(qrow1 + c0 + 8);
        }
    }

    float o[8][4];
    #pragma unroll
    for (int j = 0; j < 8; j++) { o[j][0] = 0.f; o[j][1] = 0.f; o[j][2] = 0.f; o[j][3] = 0.f; }
    float m0 = -CUDART_INF_F, m1 = -CUDART_INF_F;
    float l0 = 0.f, l1 = 0.f;

    unsigned paA[4][4], paB[4][4];

    // PV of tile tp using fragments pr, accumulating into o
    auto pv = [&](int tp, const unsigned (&pr)[4][4]) {
        const unsigned vst = vbase + (tp & 3) * STAGE_B;
        #pragma unroll
        for (int jd = 0; jd < 8; jd++) {
            #pragma unroll
            for (int kk2 = 0; kk2 < 2; kk2++) {
                unsigned b0, b1, b2, b3;
                ldsm_x4tu(b0, b1, b2, b3, vst + kk2 * (32 * KPAD * 2) + jd * 16);
                mma16816(o[jd], pr[2 * kk2],     b0, b1);
                mma16816(o[jd], pr[2 * kk2 + 1], b2, b3);
            }
        }
    };

    // one tile body: wait/barrier/prefetch, S=QK(t), softmax -> pw, PV(t-1) with pr, rescale
    auto body = [&](int t, const unsigned (&pr)[4][4], unsigned (&pw)[4][4], bool doPV) {
        asm volatile("cp.async.wait_group 2;\n");
        __syncthreads();
        fillK(t + 3);
        fillV(t + 2);
        asm volatile("cp.async.commit_group;\n");

        // ---- S = Q K^T ----
        float s[8][4];
        #pragma unroll
        for (int j = 0; j < 8; j++) { s[j][0] = 0.f; s[j][1] = 0.f; s[j][2] = 0.f; s[j][3] = 0.f; }
        const unsigned kst = kbase + (t & 3) * STAGE_B;
        #pragma unroll
        for (int j = 0; j < 8; j++) {
            #pragma unroll
            for (int kk2 = 0; kk2 < 2; kk2++) {
                unsigned b0, b1, b2, b3;
                ldsm_x4u(b0, b1, b2, b3, kst + j * (8 * KPAD * 2) + kk2 * 64);
                mma16816(s[j], qa[2 * kk2],     b0, b1);
                mma16816(s[j], qa[2 * kk2 + 1], b2, b3);
            }
        }

        // ---- softmax part 1: row max ----
        float rm0 = -CUDART_INF_F, rm1 = -CUDART_INF_F;
        #pragma unroll
        for (int j = 0; j < 8; j++) {
            rm0 = fmaxf(rm0, fmaxf(s[j][0], s[j][1]));
            rm1 = fmaxf(rm1, fmaxf(s[j][2], s[j][3]));
        }
        rm0 = fmaxf(rm0, __shfl_xor_sync(0xffffffffu, rm0, 1));
        rm0 = fmaxf(rm0, __shfl_xor_sync(0xffffffffu, rm0, 2));
        rm1 = fmaxf(rm1, __shfl_xor_sync(0xffffffffu, rm1, 1));
        rm1 = fmaxf(rm1, __shfl_xor_sync(0xffffffffu, rm1, 2));

        float mn0 = fmaxf(m0, rm0), mn1 = fmaxf(m1, rm1);
        float a0 = fast_exp2(m0 - mn0), a1 = fast_exp2(m1 - mn1);

        // ---- exponentials in fp16x2: result IS the mma A-fragment ----
        #pragma unroll
        for (int kk = 0; kk < 4; kk++) {
            pw[kk][0] = ex2h2(pack_h2(s[2 * kk][0] - mn0,     s[2 * kk][1] - mn0));
            pw[kk][1] = ex2h2(pack_h2(s[2 * kk][2] - mn1,     s[2 * kk][3] - mn1));
            pw[kk][2] = ex2h2(pack_h2(s[2 * kk + 1][0] - mn0, s[2 * kk + 1][1] - mn0));
            pw[kk][3] = ex2h2(pack_h2(s[2 * kk + 1][2] - mn1, s[2 * kk + 1][3] - mn1));
        }

        // row sums (fp32 accumulation from half2 exps)
        float rs0 = 0.f, rs1 = 0.f;
        #pragma unroll
        for (int kk = 0; kk < 4; kk++) {
            float2 f0 = __half22float2(*reinterpret_cast<const __half2*>(&pw[kk][0]));
            float2 f2 = __half22float2(*reinterpret_cast<const __half2*>(&pw[kk][2]));
            rs0 += (f0.x + f0.y) + (f2.x + f2.y);
            float2 f1 = __half22float2(*reinterpret_cast<const __half2*>(&pw[kk][1]));
            float2 f3 = __half22float2(*reinterpret_cast<const __half2*>(&pw[kk][3]));
            rs1 += (f1.x + f1.y) + (f3.x + f3.y);
        }
        rs0 += __shfl_xor_sync(0xffffffffu, rs0, 1);
        rs0 += __shfl_xor_sync(0xffffffffu, rs0, 2);
        rs1 += __shfl_xor_sync(0xffffffffu, rs1, 1);
        rs1 += __shfl_xor_sync(0xffffffffu, rs1, 2);

        // ---- deferred PV of previous tile (independent of softmax above:
        // HW/compiler overlaps MUFU chain with these HMMA/ldsm) ----
        if (doPV) pv(t - 1, pr);

        // ---- state update (must follow PV: o holds old-scale accumulation) ----
        #pragma unroll
        for (int j = 0; j < 8; j++) {
            o[j][0] *= a0; o[j][1] *= a0;
            o[j][2] *= a1; o[j][3] *= a1;
        }
        l0 = l0 * a0 + rs0;
        l1 = l1 * a1 + rs1;
        m0 = mn0; m1 = mn1;
    };

    // peel t=0 (writes paA), t=1 (paA -> paB), then pairs keep parity static
    body(0, paA, paA, false);
    body(1, paA, paB, true);
    #pragma unroll 1
    for (int t = 2; t < NTILES; t += 2) {
        body(t,     paB, paA, true);
        body(t + 1, paA, paB, true);
    }
    // final PV for tile 63 (fragments in paB, V stage 3 still resident)
    pv(NTILES - 1, paB);

    // ---- epilogue: normalize + output affine, direct stores ----
    float inv0 = 1.f / l0, inv1 = 1.f / l1;
    int row0 = q0 + w * 16 + gid;
    float* out0 = out + (b * SEQ + row0) * 256 + h * 64;
    float* out1 = out0 + 8 * 256;
    #pragma unroll
    for (int jd = 0; jd < 8; jd++) {
        int c = jd * 8 + tig * 2;
        float2 w2 = *(const float2*)(wp + h * 64 + c);
        float2 b2 = *(const float2*)(bp + h * 64 + c);
        float2 r0, r1;
        r0.x = o[jd][0] * inv0 * w2.x + b2.x;
        r0.y = o[jd][1] * inv0 * w2.y + b2.y;
        r1.x = o[jd][2] * inv1 * w2.x + b2.x;
        r1.y = o[jd][3] * inv1 * w2.y + b2.y;
        *(float2*)(out0 + c) = r0;
        *(float2*)(out1 + c) = r1;
    }
}

// ---------------- launch ----------------
extern "C" void kernel_launch(void* const* d_in, const int* in_sizes, int n_in,
                              void* d_out, int out_size)
{
    const float* q_in = (const float*)d_in[0];
    const float* k_in = (const float*)d_in[1];
    const float* v_in = (const float*)d_in[2];
    const float* wq = (const float*)d_in[3];
    const float* bq = (const float*)d_in[4];
    const float* wk = (const float*)d_in[5];
    const float* bk = (const float*)d_in[6];
    const float* wv = (const float*)d_in[7];
    const float* bv = (const float*)d_in[8];
    const float* wp = (const float*)d_in[9];
    const float* bp = (const float*)d_in[10];

    int B = in_sizes[0] / (SEQ * 256);   // expected 4
    int total4 = B * SEQ * 64;

    cudaFuncSetAttribute(attn_kernel, cudaFuncAttributeMaxDynamicSharedMemorySize, SMEM_BYTES);

    preprocess_kernel<<<(total4 + 255) / 256, 256>>>(
        q_in, k_in, v_in, wq, bq, wk, bk, wv, bv, total4);

    dim3 grid(SEQ / BM, B * NH);
    attn_kernel<<<grid, 256, SMEM_BYTES>>>((float*)d_out, wp, bp);
}

// round 6
// speedup vs baseline: 1.1700x; 1.1244x over previous
#include <cuda_runtime.h>
#include <cuda_fp16.h>
#include <math_constants.h>

#define SEQ 4096
#define DH 64
#define NH 4
#define BM 128          // 4 warps x 32 rows
#define BN 64
#define NTILES (SEQ / BN)
#define KPAD 72
#define TSZ (BN * KPAD)
#define STAGE_B (TSZ * 2)
#define SMEM_BYTES (8 * STAGE_B)   // 4 K + 4 V stages = 73728 B

__device__ __half g_Q[4 * NH * SEQ * DH];
__device__ __half g_K[4 * NH * SEQ * DH];
__device__ __half g_V[4 * NH * SEQ * DH];

__device__ __forceinline__ float fast_exp2(float x) {
    float y; asm("ex2.approx.f32 %0, %1;" : "=f"(y) : "f"(x)); return y;
}
__device__ __forceinline__ unsigned pack_h2(float a, float b) {
    __half2 h = __floats2half2_rn(a, b);
    return *reinterpret_cast<unsigned*>(&h);
}
__device__ __forceinline__ unsigned ex2h2(unsigned x) {
    unsigned y; asm("ex2.approx.f16x2 %0, %1;" : "=r"(y) : "r"(x)); return y;
}

// ---------------- preprocess ----------------
__global__ void preprocess_kernel(
    const float* __restrict__ q_in, const float* __restrict__ k_in, const float* __restrict__ v_in,
    const float* __restrict__ wq, const float* __restrict__ bq,
    const float* __restrict__ wk, const float* __restrict__ bk,
    const float* __restrict__ wv, const float* __restrict__ bv,
    int total4)
{
    const float qs = 0.125f * 1.44269504088896340736f;
    int i4 = blockIdx.x * blockDim.x + threadIdx.x;
    if (i4 >= total4) return;
    int c4 = i4 & 63;
    int s  = (i4 >> 6) & (SEQ - 1);
    int b  = i4 >> 18;
    int c  = c4 * 4;
    int h  = c >> 6;
    int d  = c & 63;
    int in_idx  = (b * SEQ + s) * 256 + c;
    int out_idx = ((b * NH + h) * SEQ + s) * DH + d;

    float4 qv = *(const float4*)(q_in + in_idx);
    float4 kv = *(const float4*)(k_in + in_idx);
    float4 vv = *(const float4*)(v_in + in_idx);
    float4 w, bb; uint2 p;

    w = *(const float4*)(wq + c); bb = *(const float4*)(bq + c);
    p.x = pack_h2((qv.x * w.x + bb.x) * qs, (qv.y * w.y + bb.y) * qs);
    p.y = pack_h2((qv.z * w.z + bb.z) * qs, (qv.w * w.w + bb.w) * qs);
    *(uint2*)(g_Q + out_idx) = p;

    w = *(const float4*)(wk + c); bb = *(const float4*)(bk + c);
    p.x = pack_h2(kv.x * w.x + bb.x, kv.y * w.y + bb.y);
    p.y = pack_h2(kv.z * w.z + bb.z, kv.w * w.w + bb.w);
    *(uint2*)(g_K + out_idx) = p;

    w = *(const float4*)(wv + c); bb = *(const float4*)(bv + c);
    p.x = pack_h2(vv.x * w.x + bb.x, vv.y * w.y + bb.y);
    p.y = pack_h2(vv.z * w.z + bb.z, vv.w * w.w + bb.w);
    *(uint2*)(g_V + out_idx) = p;
}

// ---------------- flash attention, 32 rows/warp ----------------
__device__ __forceinline__ void mma16816(float c[4], const unsigned a[4], unsigned b0, unsigned b1) {
    asm volatile(
        "mma.sync.aligned.m16n8k16.row.col.f32.f16.f16.f32 "
        "{%0,%1,%2,%3},{%4,%5,%6,%7},{%8,%9},{%0,%1,%2,%3};\n"
        : "+f"(c[0]), "+f"(c[1]), "+f"(c[2]), "+f"(c[3])
        : "r"(a[0]), "r"(a[1]), "r"(a[2]), "r"(a[3]), "r"(b0), "r"(b1));
}
__device__ __forceinline__ void ldsm_x4u(unsigned& r0, unsigned& r1, unsigned& r2, unsigned& r3, unsigned addr) {
    asm volatile("ldmatrix.sync.aligned.m8n8.x4.shared.b16 {%0,%1,%2,%3}, [%4];\n"
                 : "=r"(r0), "=r"(r1), "=r"(r2), "=r"(r3) : "r"(addr));
}
__device__ __forceinline__ void ldsm_x4tu(unsigned& r0, unsigned& r1, unsigned& r2, unsigned& r3, unsigned addr) {
    asm volatile("ldmatrix.sync.aligned.m8n8.x4.trans.shared.b16 {%0,%1,%2,%3}, [%4];\n"
                 : "=r"(r0), "=r"(r1), "=r"(r2), "=r"(r3) : "r"(addr));
}
__device__ __forceinline__ void cp16u(unsigned dst, const __half* src) {
    asm volatile("cp.async.cg.shared.global [%0], [%1], 16;\n" :: "r"(dst), "l"(src));
}

__global__ void __launch_bounds__(128, 2) attn_kernel(
    float* __restrict__ out, const float* __restrict__ wp, const float* __restrict__ bp)
{
    extern __shared__ __half smbuf[];
    __half* Ks = smbuf;
    __half* Vs = smbuf + 4 * TSZ;
    const unsigned ks_u = (unsigned)__cvta_generic_to_shared(Ks);
    const unsigned vs_u = (unsigned)__cvta_generic_to_shared(Vs);

    const int tid  = threadIdx.x;
    const int w    = tid >> 5;    // 0..3
    const int lane = tid & 31;
    const int gid  = lane >> 2;
    const int tig  = lane & 3;

    const int bh = blockIdx.y;
    const int b  = bh >> 2;
    const int h  = bh & 3;
    const int q0 = blockIdx.x * BM;

    const __half* Qg = g_Q + bh * (SEQ * DH);
    const __half* Kg = g_K + bh * (SEQ * DH);
    const __half* Vg = g_V + bh * (SEQ * DH);

    const unsigned kbase = ks_u + ((lane & 7) * KPAD + (lane >> 3) * 8) * 2;
    const unsigned vbase = vs_u + (lane * KPAD) * 2;

    auto fillK = [&](int f) {
        if (f >= NTILES) return;
        unsigned dst0 = ks_u + (f & 3) * STAGE_B;
        const __half* src = Kg + f * BN * DH;
        #pragma unroll
        for (int i = 0; i < 4; i++) {
            int idx = i * 128 + tid;
            int r = idx >> 3, c = idx & 7;
            cp16u(dst0 + (r * KPAD + c * 8) * 2, src + r * DH + c * 8);
        }
    };
    auto fillV = [&](int f) {
        if (f >= NTILES) return;
        unsigned dst0 = vs_u + (f & 3) * STAGE_B;
        const __half* src = Vg + f * BN * DH;
        #pragma unroll
        for (int i = 0; i < 4; i++) {
            int idx = i * 128 + tid;
            int r = idx >> 3, c = idx & 7;
            cp16u(dst0 + (r * KPAD + c * 8) * 2, src + r * DH + c * 8);
        }
    };

    fillK(0); fillV(0); asm volatile("cp.async.commit_group;\n");
    fillK(1); fillV(1); asm volatile("cp.async.commit_group;\n");
    fillK(2);           asm volatile("cp.async.commit_group;\n");

    // Q fragments for 2 m-tiles (rows w*32 + {0..15} and {16..31})
    unsigned qa[2][4][4];
    #pragma unroll
    for (int m = 0; m < 2; m++) {
        const __half* qrow0 = Qg + (q0 + w * 32 + m * 16 + gid) * DH;
        const __half* qrow1 = qrow0 + 8 * DH;
        #pragma unroll
        for (int kk = 0; kk < 4; kk++) {
            int c0 = kk * 16 + tig * 2;
            qa[m][kk][0] = *(const unsigned*)(qrow0 + c0);
            qa[m][kk][1] = *(const unsigned*)(qrow1 + c0);
            qa[m][kk][2] = *(const unsigned*)(qrow0 + c0 + 8);
            qa[m][kk][3] = *(const unsigned*)(qrow1 + c0 + 8);
        }
    }

    float o[2][8][4];
    #pragma unroll
    for (int m = 0; m < 2; m++)
        #pragma unroll
        for (int j = 0; j < 8; j++)
            { o[m][j][0]=0.f; o[m][j][1]=0.f; o[m][j][2]=0.f; o[m][j][3]=0.f; }
    float mx[4] = {-CUDART_INF_F, -CUDART_INF_F, -CUDART_INF_F, -CUDART_INF_F};
    float l[4]  = {0.f, 0.f, 0.f, 0.f};

    #pragma unroll 1
    for (int t = 0; t < NTILES; t++) {
        if (t + 1 < NTILES) asm volatile("cp.async.wait_group 2;\n");
        else                asm volatile("cp.async.wait_group 0;\n");
        __syncthreads();
        fillK(t + 3);
        fillV(t + 2);
        asm volatile("cp.async.commit_group;\n");

        // ---- S = Q K^T : one ldsm serves both m-tiles ----
        float s[2][8][4];
        #pragma unroll
        for (int m = 0; m < 2; m++)
            #pragma unroll
            for (int j = 0; j < 8; j++)
                { s[m][j][0]=0.f; s[m][j][1]=0.f; s[m][j][2]=0.f; s[m][j][3]=0.f; }
        const unsigned kst = kbase + (t & 3) * STAGE_B;
        #pragma unroll
        for (int j = 0; j < 8; j++) {
            #pragma unroll
            for (int kk2 = 0; kk2 < 2; kk2++) {
                unsigned b0, b1, b2, b3;
                ldsm_x4u(b0, b1, b2, b3, kst + j * (8 * KPAD * 2) + kk2 * 64);
                mma16816(s[0][j], qa[0][2 * kk2],     b0, b1);
                mma16816(s[0][j], qa[0][2 * kk2 + 1], b2, b3);
                mma16816(s[1][j], qa[1][2 * kk2],     b0, b1);
                mma16816(s[1][j], qa[1][2 * kk2 + 1], b2, b3);
            }
        }

        // ---- online softmax (base-2; Q pre-scaled) ----
        unsigned pa[2][4][4];
        float a[4];
        #pragma unroll
        for (int m = 0; m < 2; m++) {
            float rm0 = -CUDART_INF_F, rm1 = -CUDART_INF_F;
            #pragma unroll
            for (int j = 0; j < 8; j++) {
                rm0 = fmaxf(rm0, fmaxf(s[m][j][0], s[m][j][1]));
                rm1 = fmaxf(rm1, fmaxf(s[m][j][2], s[m][j][3]));
            }
            rm0 = fmaxf(rm0, __shfl_xor_sync(0xffffffffu, rm0, 1));
            rm0 = fmaxf(rm0, __shfl_xor_sync(0xffffffffu, rm0, 2));
            rm1 = fmaxf(rm1, __shfl_xor_sync(0xffffffffu, rm1, 1));
            rm1 = fmaxf(rm1, __shfl_xor_sync(0xffffffffu, rm1, 2));
            float mn0 = fmaxf(mx[2 * m], rm0), mn1 = fmaxf(mx[2 * m + 1], rm1);
            a[2 * m]     = fast_exp2(mx[2 * m] - mn0);
            a[2 * m + 1] = fast_exp2(mx[2 * m + 1] - mn1);
            mx[2 * m] = mn0; mx[2 * m + 1] = mn1;

            #pragma unroll
            for (int kk = 0; kk < 4; kk++) {
                pa[m][kk][0] = ex2h2(pack_h2(s[m][2 * kk][0] - mn0,     s[m][2 * kk][1] - mn0));
                pa[m][kk][1] = ex2h2(pack_h2(s[m][2 * kk][2] - mn1,     s[m][2 * kk][3] - mn1));
                pa[m][kk][2] = ex2h2(pack_h2(s[m][2 * kk + 1][0] - mn0, s[m][2 * kk + 1][1] - mn0));
                pa[m][kk][3] = ex2h2(pack_h2(s[m][2 * kk + 1][2] - mn1, s[m][2 * kk + 1][3] - mn1));
            }
            float rs0 = 0.f, rs1 = 0.f;
            #pragma unroll
            for (int kk = 0; kk < 4; kk++) {
                float2 f0 = __half22float2(*reinterpret_cast<const __half2*>(&pa[m][kk][0]));
                float2 f2 = __half22float2(*reinterpret_cast<const __half2*>(&pa[m][kk][2]));
                rs0 += (f0.x + f0.y) + (f2.x + f2.y);
                float2 f1 = __half22float2(*reinterpret_cast<const __half2*>(&pa[m][kk][1]));
                float2 f3 = __half22float2(*reinterpret_cast<const __half2*>(&pa[m][kk][3]));
                rs1 += (f1.x + f1.y) + (f3.x + f3.y);
            }
            rs0 += __shfl_xor_sync(0xffffffffu, rs0, 1);
            rs0 += __shfl_xor_sync(0xffffffffu, rs0, 2);
            rs1 += __shfl_xor_sync(0xffffffffu, rs1, 1);
            rs1 += __shfl_xor_sync(0xffffffffu, rs1, 2);
            l[2 * m]     = l[2 * m] * a[2 * m] + rs0;
            l[2 * m + 1] = l[2 * m + 1] * a[2 * m + 1] + rs1;

            #pragma unroll
            for (int j = 0; j < 8; j++) {
                o[m][j][0] *= a[2 * m];     o[m][j][1] *= a[2 * m];
                o[m][j][2] *= a[2 * m + 1]; o[m][j][3] *= a[2 * m + 1];
            }
        }

        // ---- O += P V : one trans-ldsm serves both m-tiles ----
        const unsigned vst = vbase + (t & 3) * STAGE_B;
        #pragma unroll
        for (int jd = 0; jd < 8; jd++) {
            #pragma unroll
            for (int kk2 = 0; kk2 < 2; kk2++) {
                unsigned b0, b1, b2, b3;
                ldsm_x4tu(b0, b1, b2, b3, vst + kk2 * (32 * KPAD * 2) + jd * 16);
                mma16816(o[0][jd], pa[0][2 * kk2],     b0, b1);
                mma16816(o[0][jd], pa[0][2 * kk2 + 1], b2, b3);
                mma16816(o[1][jd], pa[1][2 * kk2],     b0, b1);
                mma16816(o[1][jd], pa[1][2 * kk2 + 1], b2, b3);
            }
        }
    }

    // ---- epilogue ----
    #pragma unroll
    for (int m = 0; m < 2; m++) {
        float inv0 = 1.f / l[2 * m], inv1 = 1.f / l[2 * m + 1];
        int row0 = q0 + w * 32 + m * 16 + gid;
        float* out0 = out + (b * SEQ + row0) * 256 + h * 64;
        float* out1 = out0 + 8 * 256;
        #pragma unroll
        for (int jd = 0; jd < 8; jd++) {
            int c = jd * 8 + tig * 2;
            float2 w2 = *(const float2*)(wp + h * 64 + c);
            float2 b2 = *(const float2*)(bp + h * 64 + c);
            float2 r0, r1;
            r0.x = o[m][jd][0] * inv0 * w2.x + b2.x;
            r0.y = o[m][jd][1] * inv0 * w2.y + b2.y;
            r1.x = o[m][jd][2] * inv1 * w2.x + b2.x;
            r1.y = o[m][jd][3] * inv1 * w2.y + b2.y;
            *(float2*)(out0 + c) = r0;
            *(float2*)(out1 + c) = r1;
        }
    }
}

// ---------------- launch ----------------
extern "C" void kernel_launch(void* const* d_in, const int* in_sizes, int n_in,
                              void* d_out, int out_size)
{
    const float* q_in = (const float*)d_in[0];
    const float* k_in = (const float*)d_in[1];
    const float* v_in = (const float*)d_in[2];
    const float* wq = (const float*)d_in[3];
    const float* bq = (const float*)d_in[4];
    const float* wk = (const float*)d_in[5];
    const float* bk = (const float*)d_in[6];
    const float* wv = (const float*)d_in[7];
    const float* bv = (const float*)d_in[8];
    const float* wp = (const float*)d_in[9];
    const float* bp = (const float*)d_in[10];

    int B = in_sizes[0] / (SEQ * 256);
    int total4 = B * SEQ * 64;

    cudaFuncSetAttribute(attn_kernel, cudaFuncAttributeMaxDynamicSharedMemorySize, SMEM_BYTES);

    preprocess_kernel<<<(total4 + 255) / 256, 256>>>(
        q_in, k_in, v_in, wq, bq, wk, bk, wv, bv, total4);

    dim3 grid(SEQ / BM, B * NH);
    attn_kernel<<<grid, 128, SMEM_BYTES>>>((float*)d_out, wp, bp);
}

// round 7
// speedup vs baseline: 1.3433x; 1.1481x over previous
#include <cuda_runtime.h>
#include <cuda_fp16.h>
#include <math_constants.h>

#define SEQ 4096
#define DH 64
#define NH 4
#define BM 128          // 4 warps x 32 rows
#define BN 64
#define NTILES (SEQ / BN)
#define KPAD 72
#define TSZ (BN * KPAD)
#define STAGE_B (TSZ * 2)
#define SMEM_BYTES (8 * STAGE_B)   // 4 K + 4 V stages = 73728 B

__device__ __half g_Q[4 * NH * SEQ * DH];
__device__ __half g_K[4 * NH * SEQ * DH];
__device__ __half g_V[4 * NH * SEQ * DH];

__device__ __forceinline__ unsigned pack_h2(float a, float b) {
    __half2 h = __floats2half2_rn(a, b);
    return *reinterpret_cast<unsigned*>(&h);
}
__device__ __forceinline__ unsigned ex2h2(unsigned x) {
    unsigned y; asm("ex2.approx.f16x2 %0, %1;" : "=r"(y) : "r"(x)); return y;
}
// pack two f32 (a-m, b-m), clamp at 14, exp2 in f16x2 -> ready as mma A fragment
__device__ __forceinline__ unsigned expfrag(float a, float b, const __half2 cl) {
    __half2 h = __floats2half2_rn(a, b);
    h = __hmin2(h, cl);
    unsigned u = *reinterpret_cast<unsigned*>(&h);
    return ex2h2(u);
}

// ---------------- preprocess ----------------
__global__ void preprocess_kernel(
    const float* __restrict__ q_in, const float* __restrict__ k_in, const float* __restrict__ v_in,
    const float* __restrict__ wq, const float* __restrict__ bq,
    const float* __restrict__ wk, const float* __restrict__ bk,
    const float* __restrict__ wv, const float* __restrict__ bv,
    int total4)
{
    const float qs = 0.125f * 1.44269504088896340736f;
    int i4 = blockIdx.x * blockDim.x + threadIdx.x;
    if (i4 >= total4) return;
    int c4 = i4 & 63;
    int s  = (i4 >> 6) & (SEQ - 1);
    int b  = i4 >> 18;
    int c  = c4 * 4;
    int h  = c >> 6;
    int d  = c & 63;
    int in_idx  = (b * SEQ + s) * 256 + c;
    int out_idx = ((b * NH + h) * SEQ + s) * DH + d;

    float4 qv = *(const float4*)(q_in + in_idx);
    float4 kv = *(const float4*)(k_in + in_idx);
    float4 vv = *(const float4*)(v_in + in_idx);
    float4 w, bb; uint2 p;

    w = *(const float4*)(wq + c); bb = *(const float4*)(bq + c);
    p.x = pack_h2((qv.x * w.x + bb.x) * qs, (qv.y * w.y + bb.y) * qs);
    p.y = pack_h2((qv.z * w.z + bb.z) * qs, (qv.w * w.w + bb.w) * qs);
    *(uint2*)(g_Q + out_idx) = p;

    w = *(const float4*)(wk + c); bb = *(const float4*)(bk + c);
    p.x = pack_h2(kv.x * w.x + bb.x, kv.y * w.y + bb.y);
    p.y = pack_h2(kv.z * w.z + bb.z, kv.w * w.w + bb.w);
    *(uint2*)(g_K + out_idx) = p;

    w = *(const float4*)(wv + c); bb = *(const float4*)(bv + c);
    p.x = pack_h2(vv.x * w.x + bb.x, vv.y * w.y + bb.y);
    p.y = pack_h2(vv.z * w.z + bb.z, vv.w * w.w + bb.w);
    *(uint2*)(g_V + out_idx) = p;
}

// ---------------- flash attention, 32 rows/warp, frozen-max softmax ----------------
__device__ __forceinline__ void mma16816(float c[4], const unsigned a[4], unsigned b0, unsigned b1) {
    asm volatile(
        "mma.sync.aligned.m16n8k16.row.col.f32.f16.f16.f32 "
        "{%0,%1,%2,%3},{%4,%5,%6,%7},{%8,%9},{%0,%1,%2,%3};\n"
        : "+f"(c[0]), "+f"(c[1]), "+f"(c[2]), "+f"(c[3])
        : "r"(a[0]), "r"(a[1]), "r"(a[2]), "r"(a[3]), "r"(b0), "r"(b1));
}
__device__ __forceinline__ void ldsm_x4u(unsigned& r0, unsigned& r1, unsigned& r2, unsigned& r3, unsigned addr) {
    asm volatile("ldmatrix.sync.aligned.m8n8.x4.shared.b16 {%0,%1,%2,%3}, [%4];\n"
                 : "=r"(r0), "=r"(r1), "=r"(r2), "=r"(r3) : "r"(addr));
}
__device__ __forceinline__ void ldsm_x4tu(unsigned& r0, unsigned& r1, unsigned& r2, unsigned& r3, unsigned addr) {
    asm volatile("ldmatrix.sync.aligned.m8n8.x4.trans.shared.b16 {%0,%1,%2,%3}, [%4];\n"
                 : "=r"(r0), "=r"(r1), "=r"(r2), "=r"(r3) : "r"(addr));
}
__device__ __forceinline__ void cp16u(unsigned dst, const __half* src) {
    asm volatile("cp.async.cg.shared.global [%0], [%1], 16;\n" :: "r"(dst), "l"(src));
}

__global__ void __launch_bounds__(128, 2) attn_kernel(
    float* __restrict__ out, const float* __restrict__ wp, const float* __restrict__ bp)
{
    extern __shared__ __half smbuf[];
    __half* Ks = smbuf;
    __half* Vs = smbuf + 4 * TSZ;
    const unsigned ks_u = (unsigned)__cvta_generic_to_shared(Ks);
    const unsigned vs_u = (unsigned)__cvta_generic_to_shared(Vs);

    const int tid  = threadIdx.x;
    const int w    = tid >> 5;    // 0..3
    const int lane = tid & 31;
    const int gid  = lane >> 2;
    const int tig  = lane & 3;
    const __half2 cl = __floats2half2_rn(14.0f, 14.0f);

    const int bh = blockIdx.y;
    const int b  = bh >> 2;
    const int h  = bh & 3;
    const int q0 = blockIdx.x * BM;

    const __half* Qg = g_Q + bh * (SEQ * DH);
    const __half* Kg = g_K + bh * (SEQ * DH);
    const __half* Vg = g_V + bh * (SEQ * DH);

    const unsigned kbase = ks_u + ((lane & 7) * KPAD + (lane >> 3) * 8) * 2;
    const unsigned vbase = vs_u + (lane * KPAD) * 2;

    auto fillK = [&](int f) {
        if (f >= NTILES) return;
        unsigned dst0 = ks_u + (f & 3) * STAGE_B;
        const __half* src = Kg + f * BN * DH;
        #pragma unroll
        for (int i = 0; i < 4; i++) {
            int idx = i * 128 + tid;
            int r = idx >> 3, c = idx & 7;
            cp16u(dst0 + (r * KPAD + c * 8) * 2, src + r * DH + c * 8);
        }
    };
    auto fillV = [&](int f) {
        if (f >= NTILES) return;
        unsigned dst0 = vs_u + (f & 3) * STAGE_B;
        const __half* src = Vg + f * BN * DH;
        #pragma unroll
        for (int i = 0; i < 4; i++) {
            int idx = i * 128 + tid;
            int r = idx >> 3, c = idx & 7;
            cp16u(dst0 + (r * KPAD + c * 8) * 2, src + r * DH + c * 8);
        }
    };

    fillK(0); fillV(0); asm volatile("cp.async.commit_group;\n");
    fillK(1); fillV(1); asm volatile("cp.async.commit_group;\n");
    fillK(2);           asm volatile("cp.async.commit_group;\n");

    // Q fragments for 2 m-tiles
    unsigned qa[2][4][4];
    #pragma unroll
    for (int m = 0; m < 2; m++) {
        const __half* qrow0 = Qg + (q0 + w * 32 + m * 16 + gid) * DH;
        const __half* qrow1 = qrow0 + 8 * DH;
        #pragma unroll
        for (int kk = 0; kk < 4; kk++) {
            int c0 = kk * 16 + tig * 2;
            qa[m][kk][0] = *(const unsigned*)(qrow0 + c0);
            qa[m][kk][1] = *(const unsigned*)(qrow1 + c0);
            qa[m][kk][2] = *(const unsigned*)(qrow0 + c0 + 8);
            qa[m][kk][3] = *(const unsigned*)(qrow1 + c0 + 8);
        }
    }

    float o[2][8][4];
    #pragma unroll
    for (int m = 0; m < 2; m++)
        #pragma unroll
        for (int j = 0; j < 8; j++)
            { o[m][j][0]=0.f; o[m][j][1]=0.f; o[m][j][2]=0.f; o[m][j][3]=0.f; }
    float mx[4];                       // frozen row offsets (set at t=0)
    float l[4] = {0.f, 0.f, 0.f, 0.f}; // per-thread partial sums

    #pragma unroll 1
    for (int t = 0; t < NTILES; t++) {
        if (t + 1 < NTILES) asm volatile("cp.async.wait_group 2;\n");
        else                asm volatile("cp.async.wait_group 0;\n");
        __syncthreads();
        fillK(t + 3);
        fillV(t + 2);
        asm volatile("cp.async.commit_group;\n");

        // ---- S = Q K^T : one ldsm serves both m-tiles ----
        float s[2][8][4];
        #pragma unroll
        for (int m = 0; m < 2; m++)
            #pragma unroll
            for (int j = 0; j < 8; j++)
                { s[m][j][0]=0.f; s[m][j][1]=0.f; s[m][j][2]=0.f; s[m][j][3]=0.f; }
        const unsigned kst = kbase + (t & 3) * STAGE_B;
        #pragma unroll
        for (int j = 0; j < 8; j++) {
            #pragma unroll
            for (int kk2 = 0; kk2 < 2; kk2++) {
                unsigned b0, b1, b2, b3;
                ldsm_x4u(b0, b1, b2, b3, kst + j * (8 * KPAD * 2) + kk2 * 64);
                mma16816(s[0][j], qa[0][2 * kk2],     b0, b1);
                mma16816(s[0][j], qa[0][2 * kk2 + 1], b2, b3);
                mma16816(s[1][j], qa[1][2 * kk2],     b0, b1);
                mma16816(s[1][j], qa[1][2 * kk2 + 1], b2, b3);
            }
        }

        // ---- tile 0 only: freeze per-row reference max ----
        if (t == 0) {
            #pragma unroll
            for (int m = 0; m < 2; m++) {
                float rm0 = -CUDART_INF_F, rm1 = -CUDART_INF_F;
                #pragma unroll
                for (int j = 0; j < 8; j++) {
                    rm0 = fmaxf(rm0, fmaxf(s[m][j][0], s[m][j][1]));
                    rm1 = fmaxf(rm1, fmaxf(s[m][j][2], s[m][j][3]));
                }
                rm0 = fmaxf(rm0, __shfl_xor_sync(0xffffffffu, rm0, 1));
                rm0 = fmaxf(rm0, __shfl_xor_sync(0xffffffffu, rm0, 2));
                rm1 = fmaxf(rm1, __shfl_xor_sync(0xffffffffu, rm1, 1));
                rm1 = fmaxf(rm1, __shfl_xor_sync(0xffffffffu, rm1, 2));
                mx[2 * m]     = rm0 + 2.0f;
                mx[2 * m + 1] = rm1 + 2.0f;
            }
        }

        // ---- softmax: subtract frozen m, clamp, exp2 -> fp16 fragments; partial sums ----
        unsigned pa[2][4][4];
        #pragma unroll
        for (int m = 0; m < 2; m++) {
            const float mn0 = mx[2 * m], mn1 = mx[2 * m + 1];
            float rs0 = 0.f, rs1 = 0.f;
            #pragma unroll
            for (int kk = 0; kk < 4; kk++) {
                pa[m][kk][0] = expfrag(s[m][2 * kk][0] - mn0,     s[m][2 * kk][1] - mn0,     cl);
                pa[m][kk][1] = expfrag(s[m][2 * kk][2] - mn1,     s[m][2 * kk][3] - mn1,     cl);
                pa[m][kk][2] = expfrag(s[m][2 * kk + 1][0] - mn0, s[m][2 * kk + 1][1] - mn0, cl);
                pa[m][kk][3] = expfrag(s[m][2 * kk + 1][2] - mn1, s[m][2 * kk + 1][3] - mn1, cl);
                float2 f0 = __half22float2(*reinterpret_cast<const __half2*>(&pa[m][kk][0]));
                float2 f2 = __half22float2(*reinterpret_cast<const __half2*>(&pa[m][kk][2]));
                rs0 += (f0.x + f0.y) + (f2.x + f2.y);
                float2 f1 = __half22float2(*reinterpret_cast<const __half2*>(&pa[m][kk][1]));
                float2 f3 = __half22float2(*reinterpret_cast<const __half2*>(&pa[m][kk][3]));
                rs1 += (f1.x + f1.y) + (f3.x + f3.y);
            }
            l[2 * m]     += rs0;
            l[2 * m + 1] += rs1;
        }

        // ---- O += P V : one trans-ldsm serves both m-tiles ----
        const unsigned vst = vbase + (t & 3) * STAGE_B;
        #pragma unroll
        for (int jd = 0; jd < 8; jd++) {
            #pragma unroll
            for (int kk2 = 0; kk2 < 2; kk2++) {
                unsigned b0, b1, b2, b3;
                ldsm_x4tu(b0, b1, b2, b3, vst + kk2 * (32 * KPAD * 2) + jd * 16);
                mma16816(o[0][jd], pa[0][2 * kk2],     b0, b1);
                mma16816(o[0][jd], pa[0][2 * kk2 + 1], b2, b3);
                mma16816(o[1][jd], pa[1][2 * kk2],     b0, b1);
                mma16816(o[1][jd], pa[1][2 * kk2 + 1], b2, b3);
            }
        }
    }

    // ---- epilogue: reduce l across quad, normalize, output affine ----
    #pragma unroll
    for (int i = 0; i < 4; i++) {
        l[i] += __shfl_xor_sync(0xffffffffu, l[i], 1);
        l[i] += __shfl_xor_sync(0xffffffffu, l[i], 2);
    }
    #pragma unroll
    for (int m = 0; m < 2; m++) {
        float inv0 = 1.f / l[2 * m], inv1 = 1.f / l[2 * m + 1];
        int row0 = q0 + w * 32 + m * 16 + gid;
        float* out0 = out + (b * SEQ + row0) * 256 + h * 64;
        float* out1 = out0 + 8 * 256;
        #pragma unroll
        for (int jd = 0; jd < 8; jd++) {
            int c = jd * 8 + tig * 2;
            float2 w2 = *(const float2*)(wp + h * 64 + c);
            float2 b2 = *(const float2*)(bp + h * 64 + c);
            float2 r0, r1;
            r0.x = o[m][jd][0] * inv0 * w2.x + b2.x;
            r0.y = o[m][jd][1] * inv0 * w2.y + b2.y;
            r1.x = o[m][jd][2] * inv1 * w2.x + b2.x;
            r1.y = o[m][jd][3] * inv1 * w2.y + b2.y;
            *(float2*)(out0 + c) = r0;
            *(float2*)(out1 + c) = r1;
        }
    }
}

// ---------------- launch ----------------
extern "C" void kernel_launch(void* const* d_in, const int* in_sizes, int n_in,
                              void* d_out, int out_size)
{
    const float* q_in = (const float*)d_in[0];
    const float* k_in = (const float*)d_in[1];
    const float* v_in = (const float*)d_in[2];
    const float* wq = (const float*)d_in[3];
    const float* bq = (const float*)d_in[4];
    const float* wk = (const float*)d_in[5];
    const float* bk = (const float*)d_in[6];
    const float* wv = (const float*)d_in[7];
    const float* bv = (const float*)d_in[8];
    const float* wp = (const float*)d_in[9];
    const float* bp = (const float*)d_in[10];

    int B = in_sizes[0] / (SEQ * 256);
    int total4 = B * SEQ * 64;

    cudaFuncSetAttribute(attn_kernel, cudaFuncAttributeMaxDynamicSharedMemorySize, SMEM_BYTES);

    preprocess_kernel<<<(total4 + 255) / 256, 256>>>(
        q_in, k_in, v_in, wq, bq, wk, bk, wv, bv, total4);

    dim3 grid(SEQ / BM, B * NH);
    attn_kernel<<<grid, 128, SMEM_BYTES>>>((float*)d_out, wp, bp);
}